// round 1
// baseline (speedup 1.0000x reference)
#include <cuda_runtime.h>

#define DDIM 1024

// Small composed gate matrices, computed once per launch by k_build.
__device__ float g_R[16];   // R4[r'][r]   : product of 6 row Givens rotations
__device__ float g_C[16];   // C4[c'][c]   : product of 6 col Givens rotations
__device__ float g_H[16];   // H4[h'][h]   : product of 6 ch  Givens rotations
__device__ float g_W[256];  // W16[(r'*4+c')][(r*4+c)] = R4[r'][r]*C4[c'][c]

// ---------------------------------------------------------------------------
// Build the 4x4 composite rotations from the 18 thetas.
// Gate k on (a,b): U[a,a]=c, U[b,b]=c, U[a,b]=+s, U[b,a]=-s (identity else).
// Composite applies gate 0 first: M = G6*G5*...*G1 (left-accumulate).
// ---------------------------------------------------------------------------
__global__ void k_build(const float* __restrict__ thetas) {
    if (threadIdx.x != 0 || blockIdx.x != 0) return;
    const int pa[6] = {0, 0, 0, 1, 1, 2};
    const int pb[6] = {1, 2, 3, 2, 3, 3};
    float M[3][16];
    #pragma unroll
    for (int m = 0; m < 3; m++) {
        #pragma unroll
        for (int x = 0; x < 16; x++) M[m][x] = ((x >> 2) == (x & 3)) ? 1.0f : 0.0f;
        for (int g = 0; g < 6; g++) {
            float th = thetas[m * 6 + g];
            float c = cosf(th), s = sinf(th);
            int a = pa[g], b = pb[g];
            #pragma unroll
            for (int j = 0; j < 4; j++) {
                float ma = M[m][a * 4 + j], mb = M[m][b * 4 + j];
                M[m][a * 4 + j] =  c * ma + s * mb;   // left-mult: rows a,b mix
                M[m][b * 4 + j] = -s * ma + c * mb;
            }
        }
    }
    #pragma unroll
    for (int x = 0; x < 16; x++) { g_R[x] = M[0][x]; g_C[x] = M[1][x]; g_H[x] = M[2][x]; }
    for (int rp = 0; rp < 4; rp++)
        for (int cp = 0; cp < 4; cp++)
            for (int r = 0; r < 4; r++)
                for (int c = 0; c < 4; c++)
                    g_W[(rp * 4 + cp) * 16 + (r * 4 + c)] = M[0][rp * 4 + r] * M[1][cp * 4 + c];
}

// ---------------------------------------------------------------------------
// K1: out = (I⊗I⊗H) in (I⊗I⊗H)^T   — h-register mix on BOTH sides, fused,
// plus the copy from input into d_out. Each thread owns one 4x4 tile:
// rows i0..i0+3 (h1 = 0..3 of the same (r1,c1)), cols j0..j0+3 (h2 payload).
// grid: 256 blocks (tile-rows) x 256 threads (tile-cols). Fully coalesced.
// ---------------------------------------------------------------------------
__global__ __launch_bounds__(256) void k_hmix(const float* __restrict__ in,
                                              float* __restrict__ out) {
    __shared__ float sH[16];
    if (threadIdx.x < 16) sH[threadIdx.x] = g_H[threadIdx.x];
    __syncthreads();

    const int i0 = blockIdx.x * 4;
    const int j0 = threadIdx.x * 4;

    float v[4][4];
    #pragma unroll
    for (int r = 0; r < 4; r++) {
        float4 t = *reinterpret_cast<const float4*>(in + (size_t)(i0 + r) * DDIM + j0);
        v[r][0] = t.x; v[r][1] = t.y; v[r][2] = t.z; v[r][3] = t.w;
    }
    // left: u[r'][c] = sum_r H[r'][r] * v[r][c]
    float u[4][4];
    #pragma unroll
    for (int rp = 0; rp < 4; rp++) {
        #pragma unroll
        for (int c = 0; c < 4; c++) {
            u[rp][c] = sH[rp * 4 + 0] * v[0][c] + sH[rp * 4 + 1] * v[1][c]
                     + sH[rp * 4 + 2] * v[2][c] + sH[rp * 4 + 3] * v[3][c];
        }
    }
    // right: o[r'][c'] = sum_c u[r'][c] * H[c'][c]
    #pragma unroll
    for (int rp = 0; rp < 4; rp++) {
        float4 o;
        o.x = u[rp][0] * sH[0]  + u[rp][1] * sH[1]  + u[rp][2] * sH[2]  + u[rp][3] * sH[3];
        o.y = u[rp][0] * sH[4]  + u[rp][1] * sH[5]  + u[rp][2] * sH[6]  + u[rp][3] * sH[7];
        o.z = u[rp][0] * sH[8]  + u[rp][1] * sH[9]  + u[rp][2] * sH[10] + u[rp][3] * sH[11];
        o.w = u[rp][0] * sH[12] + u[rp][1] * sH[13] + u[rp][2] * sH[14] + u[rp][3] * sH[15];
        *reinterpret_cast<float4*>(out + (size_t)(i0 + rp) * DDIM + j0) = o;
    }
}

// ---------------------------------------------------------------------------
// K2: in-place LEFT mix over (r,c) registers: out <- (Rf⊗Cf⊗I4) out.
// Only rows with r<4 or c<4 are affected. Each thread owns one complete
// row-mixing group (all reads precede all writes), so in-place is safe.
//   path A (blocks   0..15 ): r<4 & c<4 : 16-row groups, weights W16
//   path B (blocks  16..207): r<4, c>=4 :  4-row groups, weights R4
//   path C (blocks 208..399): r>=4, c<4 :  4-row groups, weights C4
// Column index varies fastest across threads -> coalesced loads/stores.
// ---------------------------------------------------------------------------
__global__ __launch_bounds__(256) void k_left(float* __restrict__ out) {
    __shared__ float sW[256], sR[16], sC[16];
    sW[threadIdx.x] = g_W[threadIdx.x];
    if (threadIdx.x < 16) { sR[threadIdx.x] = g_R[threadIdx.x]; sC[threadIdx.x] = g_C[threadIdx.x]; }
    __syncthreads();

    const int b = blockIdx.x;
    if (b < 16) {
        int idx = b * 256 + threadIdx.x;        // 0..4095
        int h   = idx >> 10;                    // 0..3
        int col = idx & 1023;
        float x[16];
        #pragma unroll
        for (int k = 0; k < 16; k++) {
            int r = k >> 2, c = k & 3;
            x[k] = out[(size_t)((r << 6) + (c << 2) + h) * DDIM + col];
        }
        #pragma unroll
        for (int kp = 0; kp < 16; kp++) {
            float acc = 0.0f;
            #pragma unroll
            for (int k = 0; k < 16; k++) acc += sW[kp * 16 + k] * x[k];
            int r = kp >> 2, c = kp & 3;
            out[(size_t)((r << 6) + (c << 2) + h) * DDIM + col] = acc;
        }
    } else if (b < 208) {
        int idx = (b - 16) * 256 + threadIdx.x; // 0..49151
        int ch  = idx >> 10;                    // 0..47
        int c   = 4 + (ch >> 2);
        int h   = ch & 3;
        int col = idx & 1023;
        float x[4];
        #pragma unroll
        for (int r = 0; r < 4; r++)
            x[r] = out[(size_t)((r << 6) + (c << 2) + h) * DDIM + col];
        #pragma unroll
        for (int rp = 0; rp < 4; rp++) {
            float acc = sR[rp*4+0]*x[0] + sR[rp*4+1]*x[1] + sR[rp*4+2]*x[2] + sR[rp*4+3]*x[3];
            out[(size_t)((rp << 6) + (c << 2) + h) * DDIM + col] = acc;
        }
    } else {
        int idx = (b - 208) * 256 + threadIdx.x;
        int rh  = idx >> 10;                    // 0..47
        int r   = 4 + (rh >> 2);
        int h   = rh & 3;
        int col = idx & 1023;
        float x[4];
        #pragma unroll
        for (int c = 0; c < 4; c++)
            x[c] = out[(size_t)((r << 6) + (c << 2) + h) * DDIM + col];
        #pragma unroll
        for (int cp = 0; cp < 4; cp++) {
            float acc = sC[cp*4+0]*x[0] + sC[cp*4+1]*x[1] + sC[cp*4+2]*x[2] + sC[cp*4+3]*x[3];
            out[(size_t)((r << 6) + (cp << 2) + h) * DDIM + col] = acc;
        }
    }
}

// ---------------------------------------------------------------------------
// K3: in-place RIGHT mix over (r2,c2) column registers: out <- out (Rf⊗Cf⊗I4)^T.
// h2 (stride-1 in j) rides along as a float4 payload. Each thread owns one
// complete column-mixing group for one row -> in-place safe.
//   path A (blocks  0..3 ): r2<4 & c2<4 : 16 float4s / thread, weights W16
//   path B (blocks  4..51): r2<4, c2>=4:  4 float4s, weights R4
//   path C (blocks 52..99): r2>=4, c2<4:  4 float4s, weights C4
// ---------------------------------------------------------------------------
__global__ __launch_bounds__(256) void k_right(float* __restrict__ out) {
    __shared__ float sW[256], sR[16], sC[16];
    sW[threadIdx.x] = g_W[threadIdx.x];
    if (threadIdx.x < 16) { sR[threadIdx.x] = g_R[threadIdx.x]; sC[threadIdx.x] = g_C[threadIdx.x]; }
    __syncthreads();

    const int b = blockIdx.x;
    if (b < 4) {
        int i = b * 256 + threadIdx.x;          // row 0..1023
        float* row = out + (size_t)i * DDIM;
        float4 p[16];
        #pragma unroll
        for (int k = 0; k < 16; k++) {
            int r = k >> 2, c = k & 3;
            p[k] = *reinterpret_cast<const float4*>(row + (r << 6) + (c << 2));
        }
        #pragma unroll
        for (int kp = 0; kp < 16; kp++) {
            float4 q = make_float4(0.f, 0.f, 0.f, 0.f);
            #pragma unroll
            for (int k = 0; k < 16; k++) {
                float w = sW[kp * 16 + k];
                q.x += w * p[k].x; q.y += w * p[k].y; q.z += w * p[k].z; q.w += w * p[k].w;
            }
            int r = kp >> 2, c = kp & 3;
            *reinterpret_cast<float4*>(row + (r << 6) + (c << 2)) = q;
        }
    } else if (b < 52) {
        int idx = (b - 4) * 256 + threadIdx.x;  // 0..12287
        int i   = idx & 1023;
        int c2  = 4 + (idx >> 10);              // 4..15
        float* row = out + (size_t)i * DDIM;
        float4 p[4];
        #pragma unroll
        for (int r = 0; r < 4; r++)
            p[r] = *reinterpret_cast<const float4*>(row + (r << 6) + (c2 << 2));
        #pragma unroll
        for (int rp = 0; rp < 4; rp++) {
            float4 q;
            q.x = sR[rp*4+0]*p[0].x + sR[rp*4+1]*p[1].x + sR[rp*4+2]*p[2].x + sR[rp*4+3]*p[3].x;
            q.y = sR[rp*4+0]*p[0].y + sR[rp*4+1]*p[1].y + sR[rp*4+2]*p[2].y + sR[rp*4+3]*p[3].y;
            q.z = sR[rp*4+0]*p[0].z + sR[rp*4+1]*p[1].z + sR[rp*4+2]*p[2].z + sR[rp*4+3]*p[3].z;
            q.w = sR[rp*4+0]*p[0].w + sR[rp*4+1]*p[1].w + sR[rp*4+2]*p[2].w + sR[rp*4+3]*p[3].w;
            *reinterpret_cast<float4*>(row + (rp << 6) + (c2 << 2)) = q;
        }
    } else {
        int idx = (b - 52) * 256 + threadIdx.x; // 0..12287
        int i   = idx & 1023;
        int r2  = 4 + (idx >> 10);              // 4..15
        float* row = out + (size_t)i * DDIM;
        float4 p[4];
        #pragma unroll
        for (int c = 0; c < 4; c++)
            p[c] = *reinterpret_cast<const float4*>(row + (r2 << 6) + (c << 2));
        #pragma unroll
        for (int cp = 0; cp < 4; cp++) {
            float4 q;
            q.x = sC[cp*4+0]*p[0].x + sC[cp*4+1]*p[1].x + sC[cp*4+2]*p[2].x + sC[cp*4+3]*p[3].x;
            q.y = sC[cp*4+0]*p[0].y + sC[cp*4+1]*p[1].y + sC[cp*4+2]*p[2].y + sC[cp*4+3]*p[3].y;
            q.z = sC[cp*4+0]*p[0].z + sC[cp*4+1]*p[1].z + sC[cp*4+2]*p[2].z + sC[cp*4+3]*p[3].z;
            q.w = sC[cp*4+0]*p[0].w + sC[cp*4+1]*p[1].w + sC[cp*4+2]*p[2].w + sC[cp*4+3]*p[3].w;
            *reinterpret_cast<float4*>(row + (r2 << 6) + (cp << 2)) = q;
        }
    }
}

// ---------------------------------------------------------------------------
// Inputs (metadata order): input_state (1024*1024 f32), thetas (18 f32),
// M0s/M1s/M2s (18*1024*1024 each, ignored — fully reconstructed from theory).
// Identify by element count for robustness.
// ---------------------------------------------------------------------------
extern "C" void kernel_launch(void* const* d_in, const int* in_sizes, int n_in,
                              void* d_out, int out_size) {
    const float* rho = nullptr;
    const float* thetas = nullptr;
    for (int i = 0; i < n_in; i++) {
        if (in_sizes[i] == 18 && !thetas)            thetas = (const float*)d_in[i];
        else if (in_sizes[i] == DDIM * DDIM && !rho) rho    = (const float*)d_in[i];
    }
    float* out = (float*)d_out;

    k_build<<<1, 32>>>(thetas);
    k_hmix <<<256, 256>>>(rho, out);
    k_left <<<400, 256>>>(out);
    k_right<<<100, 256>>>(out);
}

// round 2
// speedup vs baseline: 2.0090x; 2.0090x over previous
#include <cuda_runtime.h>

#define DDIM 1024

// ---------------------------------------------------------------------------
// Compose 6 Givens gates (order g=0..5, left-multiplied) into a 4x4 row-major
// matrix M: gate g on (a,b): rows a,b mix with [c s; -s c].
// ---------------------------------------------------------------------------
__device__ __forceinline__ void compose6(const float* cs, const float* sn, float* M) {
    const int pa[6] = {0, 0, 0, 1, 1, 2};
    const int pb[6] = {1, 2, 3, 2, 3, 3};
    #pragma unroll
    for (int x = 0; x < 16; x++) M[x] = ((x >> 2) == (x & 3)) ? 1.0f : 0.0f;
    #pragma unroll
    for (int g = 0; g < 6; g++) {
        float c = cs[g], s = sn[g];
        int a = pa[g], b = pb[g];
        #pragma unroll
        for (int j = 0; j < 4; j++) {
            float ma = M[a * 4 + j], mb = M[b * 4 + j];
            M[a * 4 + j] =  c * ma + s * mb;
            M[b * 4 + j] = -s * ma + c * mb;
        }
    }
}

// new[a'] = sum_a M[a'][a] * old[a]   (4-vector mix, in place via refs)
__device__ __forceinline__ void mix4(float& a0, float& a1, float& a2, float& a3,
                                     const float* M) {
    float b0 = M[0]  * a0 + M[1]  * a1 + M[2]  * a2 + M[3]  * a3;
    float b1 = M[4]  * a0 + M[5]  * a1 + M[6]  * a2 + M[7]  * a3;
    float b2 = M[8]  * a0 + M[9]  * a1 + M[10] * a2 + M[11] * a3;
    float b3 = M[12] * a0 + M[13] * a1 + M[14] * a2 + M[15] * a3;
    a0 = b0; a1 = b1; a2 = b2; a3 = b3;
}

// Per-block weight build: 18 parallel sincos, 3-thread compose into sR/sC/sH.
// Caller must __syncthreads() before AND relies on the final sync here.
__device__ __forceinline__ void build_weights(const float* __restrict__ thetas,
                                              float* sCS, float* sR, float* sC, float* sH) {
    int tid = threadIdx.x;
    if (tid < 18) {
        float s, c;
        __sincosf(thetas[tid], &s, &c);
        sCS[tid] = c;
        sCS[18 + tid] = s;
    }
    __syncthreads();
    if (tid < 3) {
        float M[16];
        compose6(&sCS[tid * 6], &sCS[18 + tid * 6], M);
        float* dst = (tid == 0) ? sR : (tid == 1 ? sC : sH);
        #pragma unroll
        for (int x = 0; x < 16; x++) dst[x] = M[x];
    }
    __syncthreads();
}

// ---------------------------------------------------------------------------
// Kernel L: out = (Rf ⊗ Cf ⊗ H) * in      (left/row mix, fully fused)
// Row i = r*64 + c*4 + h  (r,c in 0..15, h in 0..3).
// h always mixes; r mixes iff r<4; c mixes iff c<4. Closed row groups:
//   unit 0      : r<4, c<4          -> 64 rows   (H, R, C stages)
//   units 1..12 : r<4, c=unit+3     -> 16 rows   (H, R)
//   units 13..24: r=unit-9, c<4     -> 16 rows   (H, C)
//   units 25..  : r,c >= 4          ->  4 rows   (H)
// Thread = one column; loads/stores coalesced across the warp.
// grid = (4 column chunks, 169 units) x 256 threads.
// ---------------------------------------------------------------------------
__global__ __launch_bounds__(256) void k_left2(const float* __restrict__ thetas,
                                               const float* __restrict__ in,
                                               float* __restrict__ out) {
    __shared__ float sCS[36], sR[16], sC[16], sH[16];
    build_weights(thetas, sCS, sR, sC, sH);

    const int col = blockIdx.x * 256 + threadIdx.x;
    const int u = blockIdx.y;

    if (u == 0) {
        // 64-row group: r,c,h all in 0..3; x[r*16 + c*4 + h]
        float x[64];
        #pragma unroll
        for (int r = 0; r < 4; r++)
            #pragma unroll
            for (int c = 0; c < 4; c++)
                #pragma unroll
                for (int h = 0; h < 4; h++)
                    x[r * 16 + c * 4 + h] = in[(size_t)(r * 64 + c * 4 + h) * DDIM + col];
        #pragma unroll
        for (int r = 0; r < 4; r++)
            #pragma unroll
            for (int c = 0; c < 4; c++)
                mix4(x[r*16+c*4+0], x[r*16+c*4+1], x[r*16+c*4+2], x[r*16+c*4+3], sH);
        #pragma unroll
        for (int c = 0; c < 4; c++)
            #pragma unroll
            for (int h = 0; h < 4; h++)
                mix4(x[0*16+c*4+h], x[1*16+c*4+h], x[2*16+c*4+h], x[3*16+c*4+h], sR);
        #pragma unroll
        for (int r = 0; r < 4; r++)
            #pragma unroll
            for (int h = 0; h < 4; h++)
                mix4(x[r*16+0*4+h], x[r*16+1*4+h], x[r*16+2*4+h], x[r*16+3*4+h], sC);
        #pragma unroll
        for (int r = 0; r < 4; r++)
            #pragma unroll
            for (int c = 0; c < 4; c++)
                #pragma unroll
                for (int h = 0; h < 4; h++)
                    out[(size_t)(r * 64 + c * 4 + h) * DDIM + col] = x[r * 16 + c * 4 + h];
    } else if (u <= 12) {
        // r<4, fixed c = u+3: 16 rows; x[r*4+h]; stages H then R
        const int c = u + 3;
        float x[16];
        #pragma unroll
        for (int r = 0; r < 4; r++)
            #pragma unroll
            for (int h = 0; h < 4; h++)
                x[r * 4 + h] = in[(size_t)(r * 64 + c * 4 + h) * DDIM + col];
        #pragma unroll
        for (int r = 0; r < 4; r++)
            mix4(x[r*4+0], x[r*4+1], x[r*4+2], x[r*4+3], sH);
        #pragma unroll
        for (int h = 0; h < 4; h++)
            mix4(x[0*4+h], x[1*4+h], x[2*4+h], x[3*4+h], sR);
        #pragma unroll
        for (int r = 0; r < 4; r++)
            #pragma unroll
            for (int h = 0; h < 4; h++)
                out[(size_t)(r * 64 + c * 4 + h) * DDIM + col] = x[r * 4 + h];
    } else if (u <= 24) {
        // fixed r = u-9, c<4: 16 consecutive rows; x[c*4+h]; stages H then C
        const int r = u - 9;
        float x[16];
        #pragma unroll
        for (int c = 0; c < 4; c++)
            #pragma unroll
            for (int h = 0; h < 4; h++)
                x[c * 4 + h] = in[(size_t)(r * 64 + c * 4 + h) * DDIM + col];
        #pragma unroll
        for (int c = 0; c < 4; c++)
            mix4(x[c*4+0], x[c*4+1], x[c*4+2], x[c*4+3], sH);
        #pragma unroll
        for (int h = 0; h < 4; h++)
            mix4(x[0*4+h], x[1*4+h], x[2*4+h], x[3*4+h], sC);
        #pragma unroll
        for (int c = 0; c < 4; c++)
            #pragma unroll
            for (int h = 0; h < 4; h++)
                out[(size_t)(r * 64 + c * 4 + h) * DDIM + col] = x[c * 4 + h];
    } else {
        // r>=4, c>=4: 4 rows, H only
        const int idx = u - 25;            // 0..143
        const int r = 4 + idx / 12;
        const int c = 4 + idx % 12;
        const size_t base = (size_t)(r * 64 + c * 4) * DDIM + col;
        float x0 = in[base + 0 * DDIM];
        float x1 = in[base + 1 * DDIM];
        float x2 = in[base + 2 * DDIM];
        float x3 = in[base + 3 * DDIM];
        mix4(x0, x1, x2, x3, sH);
        out[base + 0 * DDIM] = x0;
        out[base + 1 * DDIM] = x1;
        out[base + 2 * DDIM] = x2;
        out[base + 3 * DDIM] = x3;
    }
}

// ---------------------------------------------------------------------------
// Kernel R: out = out * (Rf ⊗ Cf ⊗ H)^T   (right/column mix, in place)
// Block owns 4 complete rows staged in SMEM (16KB). Loads and stores are
// float4-coalesced; the three column-mix stages happen in SMEM:
//   stage H : every aligned quad (h2 = low 2 bits of j)
//   stage R : columns j<256, groups {j0, j0+64, j0+128, j0+192}
//   stage C : columns with (j&63)<16, groups {base, base+4, base+8, base+12}
// 256 blocks x 256 threads.
// ---------------------------------------------------------------------------
__global__ __launch_bounds__(256) void k_right2(const float* __restrict__ thetas,
                                                float* __restrict__ out) {
    __shared__ float sCS[36], sR[16], sC[16], sH[16];
    __shared__ float s[4 * DDIM];
    build_weights(thetas, sCS, sR, sC, sH);

    const int tid = threadIdx.x;
    float4* s4 = reinterpret_cast<float4*>(s);
    float4* g4 = reinterpret_cast<float4*>(out + (size_t)blockIdx.x * 4 * DDIM);

    // Load 4 rows, coalesced
    #pragma unroll
    for (int k = 0; k < 4; k++)
        s4[tid + 256 * k] = g4[tid + 256 * k];
    __syncthreads();

    // Stage H: each aligned quad is {h2=0..3} of one (r2,c2)
    #pragma unroll
    for (int k = 0; k < 4; k++) {
        float4 q = s4[tid + 256 * k];
        mix4(q.x, q.y, q.z, q.w, sH);
        s4[tid + 256 * k] = q;
    }
    __syncthreads();

    // Stage R: r2-mix on columns j<256. 64 groups/row x 4 rows = 256 threads.
    {
        const int row = tid >> 6;
        const int j0 = tid & 63;
        float* p = s + row * DDIM;
        mix4(p[j0], p[j0 + 64], p[j0 + 128], p[j0 + 192], sR);
    }
    __syncthreads();

    // Stage C: c2-mix on columns with c2<4. 64 groups/row x 4 rows.
    {
        const int row = tid >> 6;
        const int g = tid & 63;
        const int r2 = g >> 2, h2 = g & 3;
        float* p = s + row * DDIM + r2 * 64 + h2;
        mix4(p[0], p[4], p[8], p[12], sC);
    }
    __syncthreads();

    // Store, coalesced
    #pragma unroll
    for (int k = 0; k < 4; k++)
        g4[tid + 256 * k] = s4[tid + 256 * k];
}

// ---------------------------------------------------------------------------
// Inputs (by element count): thetas (18), input_state (1024*1024).
// M0s/M1s/M2s (18*1024*1024 each) are ignored — reconstructed analytically.
// ---------------------------------------------------------------------------
extern "C" void kernel_launch(void* const* d_in, const int* in_sizes, int n_in,
                              void* d_out, int out_size) {
    const float* rho = nullptr;
    const float* thetas = nullptr;
    for (int i = 0; i < n_in; i++) {
        if (in_sizes[i] == 18 && !thetas)            thetas = (const float*)d_in[i];
        else if (in_sizes[i] == DDIM * DDIM && !rho) rho    = (const float*)d_in[i];
    }
    float* out = (float*)d_out;

    dim3 gridL(4, 169);
    k_left2 <<<gridL, 256>>>(thetas, rho, out);
    k_right2<<<256, 256>>>(thetas, out);
}

// round 5
// speedup vs baseline: 2.4036x; 1.1964x over previous
#include <cuda_runtime.h>

#define DDIM 1024
#define PAD 65   // 64+1: stride-1 AND stride-65 smem accesses both conflict-free

// ---------------------------------------------------------------------------
// Compose 6 Givens gates (g=0..5, gate 0 applied first) into 4x4 row-major M.
// Gate g on (a,b): rows a,b mix with [c s; -s c].
// ---------------------------------------------------------------------------
__device__ __forceinline__ void compose6(const float* __restrict__ th, float* M) {
    const int pa[6] = {0, 0, 0, 1, 1, 2};
    const int pb[6] = {1, 2, 3, 2, 3, 3};
    #pragma unroll
    for (int x = 0; x < 16; x++) M[x] = ((x >> 2) == (x & 3)) ? 1.0f : 0.0f;
    #pragma unroll
    for (int g = 0; g < 6; g++) {
        float s, c;
        __sincosf(th[g], &s, &c);
        int a = pa[g], b = pb[g];
        #pragma unroll
        for (int j = 0; j < 4; j++) {
            float ma = M[a * 4 + j], mb = M[b * 4 + j];
            M[a * 4 + j] =  c * ma + s * mb;
            M[b * 4 + j] = -s * ma + c * mb;
        }
    }
}

// 4-point mix on strided smem pointer: p[k*st] <- sum_j M[k][j] * p[j*st]
__device__ __forceinline__ void mix4p(float* p, int st, const float* M) {
    float a0 = p[0], a1 = p[st], a2 = p[2 * st], a3 = p[3 * st];
    p[0]      = M[0]  * a0 + M[1]  * a1 + M[2]  * a2 + M[3]  * a3;
    p[st]     = M[4]  * a0 + M[5]  * a1 + M[6]  * a2 + M[7]  * a3;
    p[2 * st] = M[8]  * a0 + M[9]  * a1 + M[10] * a2 + M[11] * a3;
    p[3 * st] = M[12] * a0 + M[13] * a1 + M[14] * a2 + M[15] * a3;
}

// ---------------------------------------------------------------------------
// Fully fused: out = (Rf⊗Cf⊗H) in (Rf⊗Cf⊗H)^T in ONE pass over 256
// independent 64x64 tiles (closed index sets on both sides).
//   set a<4 : r<4, c in [4a,4a+4); local lr = r*16 + cl*4 + h
//             stages H(stride1), R(stride16), C(stride4, only a==0)
//   set a>=4: rows [64a,64a+64); local lr = c*4 + h
//             stages H(stride1), C(stride4 on lr<16)
// Block = 1024 threads = one tile. Thread owns one h2-quad (float4):
// column-H applied in registers at load; remaining stages staged in padded
// SMEM; global loads/stores float4-coalesced. Barriers for skipped stages
// are elided (stage conditions are uniform per block).
// ---------------------------------------------------------------------------
__global__ __launch_bounds__(1024) void k_fused(const float* __restrict__ thetas,
                                                const float* __restrict__ in,
                                                float* __restrict__ out) {
    __shared__ float sR[16], sC[16], sH[16];
    __shared__ float s[64 * PAD];

    const int tid = threadIdx.x;
    const int ac = blockIdx.x;
    const int ar = blockIdx.y;

    const int lr = tid >> 4;        // 0..63 tile row
    const int lc = (tid & 15) << 2; // 0,4,...,60 tile col (quad base)

    const int gr = (ar < 4) ? ((lr & ~15) << 2) + (ar << 4) + (lr & 15) : (ar << 6) + lr;
    const int gc = (ac < 4) ? ((lc & ~15) << 2) + (ac << 4) + (lc & 15) : (ac << 6) + lc;

    // Issue the tile load first: its latency hides the weight build below.
    const float4 v = *reinterpret_cast<const float4*>(in + (size_t)gr * DDIM + gc);

    // Weight build: threads 0..2 each compose their register's 6 gates.
    if (tid < 3) {
        float M[16];
        compose6(thetas + tid * 6, M);
        float* dst = (tid == 0) ? sR : (tid == 1 ? sC : sH);
        #pragma unroll
        for (int x = 0; x < 16; x++) dst[x] = M[x];
    }
    __syncthreads();

    // Column-H in registers (the float4 IS one h2-quad), then stage to SMEM.
    {
        float b0 = sH[0]  * v.x + sH[1]  * v.y + sH[2]  * v.z + sH[3]  * v.w;
        float b1 = sH[4]  * v.x + sH[5]  * v.y + sH[6]  * v.z + sH[7]  * v.w;
        float b2 = sH[8]  * v.x + sH[9]  * v.y + sH[10] * v.z + sH[11] * v.w;
        float b3 = sH[12] * v.x + sH[13] * v.y + sH[14] * v.z + sH[15] * v.w;
        float* sp = s + lr * PAD + lc;
        sp[0] = b0; sp[1] = b1; sp[2] = b2; sp[3] = b3;
    }
    __syncthreads();

    const int g16 = tid >> 6;   // 0..15 : group selector
    const int e64 = tid & 63;   // 0..63 : element within stage

    // ---- row-direction stages (mix across lr, fixed column e64) ----
    // H_r: quads {4q..4q+3}
    mix4p(&s[(g16 << 2) * PAD + e64], PAD, sH);

    // R_r: groups {m, m+16, m+32, m+48} (sets a<4 only)
    if (ar < 4) {
        __syncthreads();
        mix4p(&s[g16 * PAD + e64], 16 * PAD, sR);
    }
    // C_r: a==0 -> 16 groups base r*16+h stride 4; a>=4 -> rows lr<16 only
    if (ar == 0) {
        __syncthreads();
        mix4p(&s[(((g16 >> 2) << 4) + (g16 & 3)) * PAD + e64], 4 * PAD, sC);
    } else if (ar >= 4) {
        __syncthreads();
        if (tid < 256) mix4p(&s[(tid >> 6) * PAD + (tid & 63)], 4 * PAD, sC);
    }
    __syncthreads();

    // ---- column-direction stages (mix across lc, fixed row e64) ----
    // R_c: groups {m, m+16, m+32, m+48}
    if (ac < 4) {
        mix4p(&s[e64 * PAD + g16], 16, sR);
        __syncthreads();
    }
    // C_c
    if (ac == 0) {
        mix4p(&s[e64 * PAD + ((g16 >> 2) << 4) + (g16 & 3)], 4, sC);
        __syncthreads();
    } else if (ac >= 4) {
        if (tid < 256) mix4p(&s[(tid & 63) * PAD + (tid >> 6)], 4, sC);
        __syncthreads();
    }

    // Store, float4-coalesced
    {
        const float* sp = s + lr * PAD + lc;
        float4 w;
        w.x = sp[0]; w.y = sp[1]; w.z = sp[2]; w.w = sp[3];
        *reinterpret_cast<float4*>(out + (size_t)gr * DDIM + gc) = w;
    }
}

// ---------------------------------------------------------------------------
// Inputs (by element count): thetas (18), input_state (1024*1024).
// M0s/M1s/M2s (18M elements each) are ignored — reconstructed analytically.
// ---------------------------------------------------------------------------
extern "C" void kernel_launch(void* const* d_in, const int* in_sizes, int n_in,
                              void* d_out, int out_size) {
    const float* rho = nullptr;
    const float* thetas = nullptr;
    for (int i = 0; i < n_in; i++) {
        if (in_sizes[i] == 18 && !thetas)            thetas = (const float*)d_in[i];
        else if (in_sizes[i] == DDIM * DDIM && !rho) rho    = (const float*)d_in[i];
    }
    float* out = (float*)d_out;

    dim3 grid(16, 16);
    k_fused<<<grid, 1024>>>(thetas, rho, out);
}

// round 9
// speedup vs baseline: 2.4834x; 1.0332x over previous
#include <cuda_runtime.h>

#define DDIM 1024
#define PAD 65   // stride-1 AND stride-65 smem accesses both conflict-free

// ---------------------------------------------------------------------------
// Compose 6 Givens gates (g=0..5, gate 0 applied first) into 4x4 row-major M.
// ---------------------------------------------------------------------------
__device__ __forceinline__ void compose6(const float* __restrict__ th, float* M) {
    const int pa[6] = {0, 0, 0, 1, 1, 2};
    const int pb[6] = {1, 2, 3, 2, 3, 3};
    #pragma unroll
    for (int x = 0; x < 16; x++) M[x] = ((x >> 2) == (x & 3)) ? 1.0f : 0.0f;
    #pragma unroll
    for (int g = 0; g < 6; g++) {
        float s, c;
        __sincosf(th[g], &s, &c);
        int a = pa[g], b = pb[g];
        #pragma unroll
        for (int j = 0; j < 4; j++) {
            float ma = M[a * 4 + j], mb = M[b * 4 + j];
            M[a * 4 + j] =  c * ma + s * mb;
            M[b * 4 + j] = -s * ma + c * mb;
        }
    }
}

// 4-point mix, register weights, register data
__device__ __forceinline__ void mix4r(float& a0, float& a1, float& a2, float& a3,
                                      const float* M) {
    float b0 = M[0]  * a0 + M[1]  * a1 + M[2]  * a2 + M[3]  * a3;
    float b1 = M[4]  * a0 + M[5]  * a1 + M[6]  * a2 + M[7]  * a3;
    float b2 = M[8]  * a0 + M[9]  * a1 + M[10] * a2 + M[11] * a3;
    float b3 = M[12] * a0 + M[13] * a1 + M[14] * a2 + M[15] * a3;
    a0 = b0; a1 = b1; a2 = b2; a3 = b3;
}

// 4-point mix on strided smem pointer, register weights
__device__ __forceinline__ void mix4p(float* p, int st, const float* M) {
    float a0 = p[0], a1 = p[st], a2 = p[2 * st], a3 = p[3 * st];
    p[0]      = M[0]  * a0 + M[1]  * a1 + M[2]  * a2 + M[3]  * a3;
    p[st]     = M[4]  * a0 + M[5]  * a1 + M[6]  * a2 + M[7]  * a3;
    p[2 * st] = M[8]  * a0 + M[9]  * a1 + M[10] * a2 + M[11] * a3;
    p[3 * st] = M[12] * a0 + M[13] * a1 + M[14] * a2 + M[15] * a3;
}

// ---------------------------------------------------------------------------
// out = (Rf⊗Cf⊗H) in (Rf⊗Cf⊗H)^T over 256 independent 64x64 tiles.
// Index i = r*64 + c*4 + h. Closed sets:
//   set a<4 : r<4, c in [4a,4a+4): local lr = r*16 + cl*4 + h
//   set a>=4: rows [64a,64a+64):   local lr = c*4 + h
// The 16-element chain {m*16 + cl*4 + h : m,h in 0..3} (fixed cl) is closed
// under H (stride 1) and R (stride 16); only C (stride 4) crosses chains and
// is handled by small smem fixups. Block = 256 threads = one tile,
// 16 elements/thread; weights composed per block, registers thereafter.
// ---------------------------------------------------------------------------
__global__ __launch_bounds__(256) void k_fused(const float* __restrict__ thetas,
                                               const float* __restrict__ in,
                                               float* __restrict__ out) {
    __shared__ float sW[48];            // [0:16)=R, [16:32)=C, [32:48)=H
    __shared__ float s[64 * PAD];

    const int tid = threadIdx.x;
    const int ac = blockIdx.x;
    const int ar = blockIdx.y;

    const int cl  = tid >> 6;           // 0..3  row-chain selector
    const int col = tid & 63;           // 0..63 tile column
    const int gc1 = (ac < 4) ? ((col & ~15) << 2) + (ac << 4) + (col & 15)
                             : (ac << 6) + col;

    // ---- issue the 16 LDGs first; their latency hides the weight build ----
    float x[16];
    #pragma unroll
    for (int r = 0; r < 4; r++)
        #pragma unroll
        for (int h = 0; h < 4; h++) {
            const int lr = r * 16 + cl * 4 + h;
            const int gr = (ar < 4) ? ((lr & ~15) << 2) + (ar << 4) + (lr & 15)
                                    : (ar << 6) + lr;
            x[r * 4 + h] = in[(size_t)gr * DDIM + gc1];
        }

    // ---- weight build: threads 0..2 compose R, C, H ----
    if (tid < 3) {
        float M[16];
        compose6(thetas + tid * 6, M);
        #pragma unroll
        for (int k = 0; k < 16; k++) sW[tid * 16 + k] = M[k];
    }
    __syncthreads();

    // weights -> registers, once
    float wR[16], wC[16], wH[16];
    #pragma unroll
    for (int k = 0; k < 16; k++) { wR[k] = sW[k]; wC[k] = sW[16 + k]; wH[k] = sW[32 + k]; }

    // ---- row phase in registers: H_r always, R_r iff ar<4 ----
    #pragma unroll
    for (int r = 0; r < 4; r++)
        mix4r(x[r * 4 + 0], x[r * 4 + 1], x[r * 4 + 2], x[r * 4 + 3], wH);
    if (ar < 4) {
        #pragma unroll
        for (int h = 0; h < 4; h++)
            mix4r(x[0 + h], x[4 + h], x[8 + h], x[12 + h], wR);
    }

    // stage to smem (scalar STS, conflict-free: fixed lr, consecutive col)
    #pragma unroll
    for (int r = 0; r < 4; r++)
        #pragma unroll
        for (int h = 0; h < 4; h++)
            s[(r * 16 + cl * 4 + h) * PAD + col] = x[r * 4 + h];
    __syncthreads();

    // ---- C_r fixup (cross-chain, rows) ----
    if (ar == 0) {
        #pragma unroll
        for (int k = 0; k < 4; k++) {
            const int rh = (tid >> 6) + 4 * k;       // 0..15
            mix4p(&s[((rh >> 2) * 16 + (rh & 3)) * PAD + (tid & 63)], 4 * PAD, wC);
        }
        __syncthreads();
    } else if (ar >= 4) {
        mix4p(&s[(tid >> 6) * PAD + (tid & 63)], 4 * PAD, wC);  // rows {h,h+4,h+8,h+12}
        __syncthreads();
    }

    // ---- col phase in registers: thread (clc,row) owns col-chain of one row ----
    const int clc = tid >> 6;
    const int row = tid & 63;
    float y[16];
    #pragma unroll
    for (int r = 0; r < 4; r++)
        #pragma unroll
        for (int h = 0; h < 4; h++)
            y[r * 4 + h] = s[row * PAD + r * 16 + clc * 4 + h];

    #pragma unroll
    for (int r = 0; r < 4; r++)
        mix4r(y[r * 4 + 0], y[r * 4 + 1], y[r * 4 + 2], y[r * 4 + 3], wH);
    if (ac < 4) {
        #pragma unroll
        for (int h = 0; h < 4; h++)
            mix4r(y[0 + h], y[4 + h], y[8 + h], y[12 + h], wR);
    }

    #pragma unroll
    for (int r = 0; r < 4; r++)
        #pragma unroll
        for (int h = 0; h < 4; h++)
            s[row * PAD + r * 16 + clc * 4 + h] = y[r * 4 + h];
    __syncthreads();

    // ---- C_c fixup (cross-chain, columns) ----
    if (ac == 0) {
        #pragma unroll
        for (int k = 0; k < 4; k++) {
            const int rh = (tid >> 6) + 4 * k;
            mix4p(&s[(tid & 63) * PAD + (rh >> 2) * 16 + (rh & 3)], 4, wC);
        }
        __syncthreads();
    } else if (ac >= 4) {
        mix4p(&s[(tid & 63) * PAD + (tid >> 6)], 4, wC);        // cols {h,h+4,h+8,h+12}
        __syncthreads();
    }

    // ---- final store: thread (frow, q0) -> 4 float4s, 64B warp segments ----
    const int frow = tid >> 2;          // 0..63
    const int q0   = tid & 3;
    const int grf  = (ar < 4) ? ((frow & ~15) << 2) + (ar << 4) + (frow & 15)
                              : (ar << 6) + frow;
    #pragma unroll
    for (int k = 0; k < 4; k++) {
        const int colb = (q0 + 4 * k) * 4;          // quad base column
        const float* sp = s + frow * PAD + colb;
        float4 w;
        w.x = sp[0]; w.y = sp[1]; w.z = sp[2]; w.w = sp[3];
        const int gcf = (ac < 4) ? ((colb & ~15) << 2) + (ac << 4) + (colb & 15)
                                 : (ac << 6) + colb;
        *reinterpret_cast<float4*>(out + (size_t)grf * DDIM + gcf) = w;
    }
}

// ---------------------------------------------------------------------------
// Inputs (by element count): thetas (18), input_state (1024*1024).
// M0s/M1s/M2s (18M elements each) are ignored — reconstructed analytically.
// ---------------------------------------------------------------------------
extern "C" void kernel_launch(void* const* d_in, const int* in_sizes, int n_in,
                              void* d_out, int out_size) {
    const float* rho = nullptr;
    const float* thetas = nullptr;
    for (int i = 0; i < n_in; i++) {
        if (in_sizes[i] == 18 && !thetas)            thetas = (const float*)d_in[i];
        else if (in_sizes[i] == DDIM * DDIM && !rho) rho    = (const float*)d_in[i];
    }
    float* out = (float*)d_out;

    dim3 grid(16, 16);
    k_fused<<<grid, 256>>>(thetas, rho, out);
}